// round 4
// baseline (speedup 1.0000x reference)
#include <cuda_runtime.h>
#include <cuda_bf16.h>
#include <cstdint>

// Problem: y[b,e] = relu(sum_a action[b,a] * conv_w[e,a] + conv_b[e])
// out[b,e,h,w] = y[b,e] broadcast over 64x64 spatial.
// B=128, A=256, E=256, H=W=64. Output fp32, 512 MB -> pure HBM-write-bound.
//
// One block = 4 consecutive (b,e) planes (same b). Warp pair (2k, 2k+1)
// computes plane k's dot product (A=256) redundantly via float4 LDG +
// shuffle reduction, then each warp streams 8 KB of its plane with 16
// independent STG.128.cs per thread. No smem, no __syncthreads, 1 launch.

#define B_DIM   128
#define A_DIM   256
#define E_DIM   256
#define HW      4096                   // 64*64
#define NPLANES (B_DIM * E_DIM)        // 32768
#define PPB     4                      // planes per block
#define NBLOCKS (NPLANES / PPB)        // 8192

__global__ __launch_bounds__(256)
void fused_embed_fill_kernel(const float*  __restrict__ action,
                             const float*  __restrict__ conv_w,
                             const float*  __restrict__ conv_b,
                             float4*       __restrict__ out)
{
    const int base_plane = blockIdx.x * PPB;       // 4 planes, same b
    const int b    = base_plane >> 8;
    const int t    = threadIdx.x;
    const int w    = t >> 5;                       // warp 0..7
    const int lane = t & 31;

    const int k = w >> 1;                          // which of the 4 planes
    const int plane = base_plane + k;
    const int e = plane & 255;

    // --- dot product over A=256 (2 warps per plane, redundant) -------------
    const float4* a4 = reinterpret_cast<const float4*>(action + b * A_DIM);
    const float4* w4 = reinterpret_cast<const float4*>(conv_w + e * A_DIM);

    float4 av0 = a4[lane];
    float4 av1 = a4[lane + 32];
    float4 wv0 = w4[lane];
    float4 wv1 = w4[lane + 32];

    float s;
    s = av0.x * wv0.x;
    s = fmaf(av0.y, wv0.y, s);
    s = fmaf(av0.z, wv0.z, s);
    s = fmaf(av0.w, wv0.w, s);
    s = fmaf(av1.x, wv1.x, s);
    s = fmaf(av1.y, wv1.y, s);
    s = fmaf(av1.z, wv1.z, s);
    s = fmaf(av1.w, wv1.w, s);

    s += __shfl_xor_sync(0xFFFFFFFF, s, 16);
    s += __shfl_xor_sync(0xFFFFFFFF, s, 8);
    s += __shfl_xor_sync(0xFFFFFFFF, s, 4);
    s += __shfl_xor_sync(0xFFFFFFFF, s, 2);
    s += __shfl_xor_sync(0xFFFFFFFF, s, 1);

    const float v = fmaxf(s + __ldg(conv_b + e), 0.0f);
    const float4 v4 = make_float4(v, v, v, v);

    // --- stream this warp's 8 KB half-plane --------------------------------
    // plane = 1024 float4; warp (w&1) takes halves [0,512) or [512,1024).
    float4* p = out + (size_t)plane * (HW / 4) + (w & 1) * 512 + lane;

#pragma unroll
    for (int i = 0; i < 16; ++i)
        __stcs(p + i * 32, v4);
}

extern "C" void kernel_launch(void* const* d_in, const int* in_sizes, int n_in,
                              void* d_out, int out_size)
{
    const float* action = (const float*)d_in[0];   // [128, 256]
    const float* conv_w = (const float*)d_in[1];   // [256, 256]
    const float* conv_b = (const float*)d_in[2];   // [256]
    float4* out = (float4*)d_out;                  // [128, 256, 64, 64] fp32

    fused_embed_fill_kernel<<<NBLOCKS, 256>>>(action, conv_w, conv_b, out);
}

// round 5
// speedup vs baseline: 1.0216x; 1.0216x over previous
#include <cuda_runtime.h>
#include <cuda_bf16.h>
#include <cstdint>

// Problem: y[b,e] = relu(sum_a action[b,a] * conv_w[e,a] + conv_b[e])
// out[b,e,h,w] = y[b,e] broadcast over 64x64 spatial.
// B=128, A=256, E=256, H=W=64. Output fp32, 512 MB -> pure HBM-write-bound.
//
// Round-2 champion shape (one block per plane, 8 warps redundant dot,
// 4x STG.128 per thread) with ONE change: default write-back stores
// instead of __stcs streaming stores (A/B on the cache hint).

#define B_DIM   128
#define A_DIM   256
#define E_DIM   256
#define HW      4096                 // 64*64
#define NPLANES (B_DIM * E_DIM)      // 32768

__global__ __launch_bounds__(256)
void fused_embed_fill_kernel(const float*  __restrict__ action,
                             const float*  __restrict__ conv_w,
                             const float*  __restrict__ conv_b,
                             float4*       __restrict__ out)
{
    const int plane = blockIdx.x;          // b*256 + e
    const int b = plane >> 8;
    const int e = plane & 255;
    const int t    = threadIdx.x;
    const int lane = t & 31;

    // --- per-warp redundant dot product over A=256 -------------------------
    const float4* a4 = reinterpret_cast<const float4*>(action + b * A_DIM);
    const float4* w4 = reinterpret_cast<const float4*>(conv_w + e * A_DIM);

    float4 av0 = a4[lane];
    float4 av1 = a4[lane + 32];
    float4 wv0 = w4[lane];
    float4 wv1 = w4[lane + 32];

    float s;
    s = av0.x * wv0.x;
    s = fmaf(av0.y, wv0.y, s);
    s = fmaf(av0.z, wv0.z, s);
    s = fmaf(av0.w, wv0.w, s);
    s = fmaf(av1.x, wv1.x, s);
    s = fmaf(av1.y, wv1.y, s);
    s = fmaf(av1.z, wv1.z, s);
    s = fmaf(av1.w, wv1.w, s);

    s += __shfl_xor_sync(0xFFFFFFFF, s, 16);
    s += __shfl_xor_sync(0xFFFFFFFF, s, 8);
    s += __shfl_xor_sync(0xFFFFFFFF, s, 4);
    s += __shfl_xor_sync(0xFFFFFFFF, s, 2);
    s += __shfl_xor_sync(0xFFFFFFFF, s, 1);

    const float v = fmaxf(s + __ldg(conv_b + e), 0.0f);
    const float4 v4 = make_float4(v, v, v, v);

    // --- stream 16 KB plane fill (default write-back stores) ---------------
    float4* p = out + (size_t)plane * (HW / 4);   // 1024 float4 per plane

    p[t]       = v4;
    p[t + 256] = v4;
    p[t + 512] = v4;
    p[t + 768] = v4;
}

extern "C" void kernel_launch(void* const* d_in, const int* in_sizes, int n_in,
                              void* d_out, int out_size)
{
    const float* action = (const float*)d_in[0];   // [128, 256]
    const float* conv_w = (const float*)d_in[1];   // [256, 256]
    const float* conv_b = (const float*)d_in[2];   // [256]
    float4* out = (float4*)d_out;                  // [128, 256, 64, 64] fp32

    fused_embed_fill_kernel<<<NPLANES, 256>>>(action, conv_w, conv_b, out);
}